// round 7
// baseline (speedup 1.0000x reference)
#include <cuda_runtime.h>
#include <math.h>

#define BATCH    64
#define IN_F     512
#define OUT_F    512
#define BASIS    8
#define KB       9                   // 1 (silu/w slot) + BASIS
#define NSPLIT   38                  // split-K over i
#define CHUNK    14                  // 38*14 = 532 -> 20 zero-pad i-rows
#define IPAD     (NSPLIT * CHUNK)    // 532
#define STAGE_I  7
#define NSTAGE   2                   // 14 / 7
#define OTILE    64
#define STAGE_KK (STAGE_I * KB)      // 63
#define NOTILE   (OUT_F / OTILE)     // 8
#define TOTBLK   (NSPLIT * NOTILE)   // 304 = 2 blocks x 152 SMs
#define SMSTRIDE 68                  // padded row stride for basis transpose
#define RED_CHUNK 27                 // 27*304 = 8208 >= 8192 output float4 slots

// Scratch (__device__ globals; pad rows of g_A stay .bss-zero forever)
__device__ float g_A[IPAD * KB * BATCH];              // scalar A^T  [ik][b]
__device__ float g_part[NSPLIT * BATCH * OUT_F];      // 5 MB partials
__device__ unsigned g_b0;    // basis-done arrivals
__device__ unsigned g_arr;   // partial-done arrivals
__device__ unsigned g_done;  // self-wrapping exit counter (resets the others)

__device__ __forceinline__ void ffma2(unsigned long long& d,
                                      unsigned long long a,
                                      unsigned long long b) {
    asm("fma.rn.f32x2 %0, %1, %2, %0;" : "+l"(d) : "l"(a), "l"(b));
}
__device__ __forceinline__ float pick(unsigned long long u, int hi) {
    return __uint_as_float(hi ? (unsigned int)(u >> 32) : (unsigned int)u);
}

// ---------------------------------------------------------------------------
// Persistent kernel: basis -> grid barrier -> split-K GEMM -> grid barrier ->
// distributed reduce.  grid (38, 8) = 304 blocks, 256 threads, 2 blocks/SM.
// ---------------------------------------------------------------------------
__global__ __launch_bounds__(256, 2)
void kan_kernel(const float* __restrict__ x,
                const float* __restrict__ w,
                const float* __restrict__ c,
                float* __restrict__ out) {
    __shared__ float As2[STAGE_KK * 2 * BATCH];   // [63][128] dup'd A  = 32256 B
    __shared__ float Cs[STAGE_KK * OTILE];        // [63][64]           = 16128 B

    const int s   = blockIdx.x;               // split-K index 0..37
    const int oy  = blockIdx.y;               // o-tile 0..7
    const int o0  = oy * OTILE;
    const int tid = threadIdx.x;
    const int blkLinear = oy * NSPLIT + s;    // 0..303

    // ===== Phase 0: basis (blocks 0..127 compute 4 i-columns each) =====
    if (blkLinear < IN_F / 4) {
        const int i0 = blkLinear * 4;
        const int di = tid & 3;
        const int b  = tid >> 2;
        float xv = x[b * IN_F + i0 + di];

        float sig = __fdividef(1.0f, 1.0f + __expf(-xv));
        float tt  = 1.0f - 2.0f * __fdividef(1.0f, 1.0f + __expf(2.0f * xv));
        tt = fminf(fmaxf(tt, -1.0f + 1e-6f), 1.0f - 1e-6f);

        float* s0 = As2 + di * (KB * SMSTRIDE) + b;   // alias As2 as scratch
        s0[0]        = xv * sig;   // silu slot
        s0[SMSTRIDE] = tt;         // T_1
        float tkm2 = 1.0f, tkm1 = tt;
        #pragma unroll
        for (int k = 2; k <= BASIS; k++) {
            float tk = 2.0f * tt * tkm1 - tkm2;
            s0[k * SMSTRIDE] = tk;
            tkm2 = tkm1; tkm1 = tk;
        }
        __syncthreads();

        // 36 rows x 16 float4 coalesced stores to g_A (scalar layout)
        for (int idx = tid; idx < 4 * KB * 16; idx += 256) {
            int row = idx >> 4;
            int c4  = idx & 15;
            const float* sr = As2 + row * SMSTRIDE + c4 * 4;
            float4 v = make_float4(sr[0], sr[1], sr[2], sr[3]);
            int di2 = row / KB, k2 = row % KB;
            ((float4*)(g_A + (i0 + di2) * (KB * BATCH) + k2 * BATCH))[c4] = v;
        }
        __syncthreads();
        if (tid == 0) { __threadfence(); atomicAdd(&g_b0, 1u); }
    }
    // grid-wide wait: basis complete
    if (tid == 0) { while (*(volatile unsigned*)&g_b0 != (unsigned)(IN_F / 4)) {} }
    __syncthreads();

    // ===== Phase 1: split-K GEMM, 4b x 4o micro-tiles, dup'd-A smem =====
    const int og = tid & 15;      // o-group: fast within warp (16 distinct)
    const int bg = tid >> 4;      // b-group: 2 distinct per warp (broadcast a)
    const int ibeg = s * CHUNK;

    float2 aR[8];                 // A slab prefetch (float2 -> dup to float4)
    float  wR[2];
    float4 cR[2][2];

    unsigned long long acc[8];
    #pragma unroll
    for (int j = 0; j < 8; j++) acc[j] = 0ull;

    auto loadStage = [&](int istS) {
        const float2* srcA = (const float2*)(g_A + (size_t)istS * (KB * BATCH));
        #pragma unroll
        for (int j = 0; j < 8; j++) {
            int d = tid + j * 256;
            aR[j] = (d < STAGE_KK * BATCH / 2) ? srcA[d] : make_float2(0.f, 0.f);
        }
        #pragma unroll
        for (int j = 0; j < 2; j++) {
            int p = tid + j * 256;          // 448 slots
            if (p < STAGE_I * OTILE) {
                int ii = p >> 6, oc = p & 63;
                int i = istS + ii;
                int o = o0 + oc;
                if (i < IN_F) {
                    wR[j] = w[i * OUT_F + o];
                    const float4* cp = (const float4*)(c + ((size_t)i * OUT_F + o) * BASIS);
                    cR[j][0] = cp[0];
                    cR[j][1] = cp[1];
                } else {
                    wR[j] = 0.f;
                    cR[j][0] = make_float4(0.f, 0.f, 0.f, 0.f);
                    cR[j][1] = make_float4(0.f, 0.f, 0.f, 0.f);
                }
            }
        }
    };

    auto storeStage = [&]() {
        float4* dA = (float4*)As2;
        #pragma unroll
        for (int j = 0; j < 8; j++) {
            int d = tid + j * 256;
            if (d < STAGE_KK * BATCH / 2)
                dA[d] = make_float4(aR[j].x, aR[j].x, aR[j].y, aR[j].y);  // dup pair
        }
        #pragma unroll
        for (int j = 0; j < 2; j++) {
            int p = tid + j * 256;
            if (p < STAGE_I * OTILE) {
                int ii = p >> 6, oc = p & 63;
                float* cs = Cs + ii * (KB * OTILE) + oc;
                float wv = wR[j];
                cs[0 * OTILE] = wv;
                cs[1 * OTILE] = cR[j][0].x * wv;
                cs[2 * OTILE] = cR[j][0].y * wv;
                cs[3 * OTILE] = cR[j][0].z * wv;
                cs[4 * OTILE] = cR[j][0].w * wv;
                cs[5 * OTILE] = cR[j][1].x * wv;
                cs[6 * OTILE] = cR[j][1].y * wv;
                cs[7 * OTILE] = cR[j][1].z * wv;
                cs[8 * OTILE] = cR[j][1].w * wv;
            }
        }
    };

    auto compute = [&]() {
        #pragma unroll 9
        for (int kk = 0; kk < STAGE_KK; kk++) {
            ulonglong2 a01 = *(const ulonglong2*)&As2[kk * 128 + bg * 8];      // dup(b0),dup(b1)
            ulonglong2 a23 = *(const ulonglong2*)&As2[kk * 128 + bg * 8 + 4];  // dup(b2),dup(b3)
            ulonglong2 cv  = *(const ulonglong2*)&Cs[kk * OTILE + og * 4];     // (o0,o1),(o2,o3)
            ffma2(acc[0], a01.x, cv.x); ffma2(acc[1], a01.x, cv.y);
            ffma2(acc[2], a01.y, cv.x); ffma2(acc[3], a01.y, cv.y);
            ffma2(acc[4], a23.x, cv.x); ffma2(acc[5], a23.x, cv.y);
            ffma2(acc[6], a23.y, cv.x); ffma2(acc[7], a23.y, cv.y);
        }
    };

    loadStage(ibeg);
    #pragma unroll
    for (int st = 0; st < NSTAGE; st++) {
        storeStage();
        __syncthreads();
        if (st < NSTAGE - 1) loadStage(ibeg + (st + 1) * STAGE_I);
        compute();
        __syncthreads();
    }

    // write split-K partial: 4 batches x 4 o per thread (coalesced float4)
    float* pout = g_part + (size_t)s * (BATCH * OUT_F);
    #pragma unroll
    for (int r = 0; r < 4; r++) {
        const int b = bg * 4 + r;
        float4 v;
        v.x = pick(acc[2 * r + 0], 0); v.y = pick(acc[2 * r + 0], 1);
        v.z = pick(acc[2 * r + 1], 0); v.w = pick(acc[2 * r + 1], 1);
        *(float4*)&pout[b * OUT_F + o0 + og * 4] = v;
    }

    // ===== Phase 2: grid barrier, then distributed reduce =====
    __syncthreads();
    if (tid == 0) {
        __threadfence();
        atomicAdd(&g_arr, 1u);
        while (*(volatile unsigned*)&g_arr != (unsigned)TOTBLK) {}
    }
    __syncthreads();

    {
        const int slot = blkLinear * RED_CHUNK + tid;   // output float4 index
        if (tid < RED_CHUNK && slot < BATCH * OUT_F / 4) {
            const float4* gp = (const float4*)g_part;
            float4 sum = make_float4(0.f, 0.f, 0.f, 0.f);
            #pragma unroll
            for (int s2 = 0; s2 < NSPLIT; s2++) {
                float4 v = __ldcg(&gp[(size_t)s2 * (BATCH * OUT_F / 4) + slot]);
                sum.x += v.x; sum.y += v.y; sum.z += v.z; sum.w += v.w;
            }
            ((float4*)out)[slot] = sum;
        }
    }

    // reset counters for replay determinism (last block out resets)
    __syncthreads();
    if (tid == 0) {
        unsigned r = atomicInc(&g_done, TOTBLK - 1);   // wraps to 0
        if (r == TOTBLK - 1) {
            atomicExch(&g_arr, 0u);
            atomicExch(&g_b0, 0u);
        }
    }
}

// ---------------------------------------------------------------------------
extern "C" void kernel_launch(void* const* d_in, const int* in_sizes, int n_in,
                              void* d_out, int out_size) {
    const float* x = (const float*)d_in[0];   // (64, 512)
    const float* w = (const float*)d_in[1];   // (512, 512)
    const float* c = (const float*)d_in[2];   // (512, 512, 8)
    float* out = (float*)d_out;               // (64, 512)

    kan_kernel<<<dim3(NSPLIT, NOTILE), 256>>>(x, w, c, out);
}

// round 8
// speedup vs baseline: 1.0031x; 1.0031x over previous
#include <cuda_runtime.h>
#include <math.h>

#define BATCH    64
#define IN_F     512
#define OUT_F    512
#define BASIS    8
#define KB       9                   // 1 (silu/w slot) + BASIS
#define NSPLIT   38                  // split-K over i
#define CHUNK    14                  // 38*14 = 532 -> 20 zero-pad i-rows
#define IPAD     (NSPLIT * CHUNK)    // 532
#define STAGE_I  7
#define NSTAGE   2                   // 14 / 7
#define OTILE    128
#define STAGE_KK (STAGE_I * KB)      // 63
#define NOTILE   (OUT_F / OTILE)     // 4
#define TOTBLK   (NSPLIT * NOTILE)   // 152 = 1 block/SM, 4x residency headroom
#define SMSTRIDE 68                  // padded row stride for basis transpose
#define RED_CHUNK 54                 // 54*152 = 8208 >= 8192 output float4 slots

// Scratch (__device__ globals; pad rows of g_A stay .bss-zero forever)
__device__ float g_A[IPAD * KB * BATCH];              // scalar A^T [ik][b]
__device__ float g_part[NSPLIT * BATCH * OUT_F];      // 5 MB partials
__device__ unsigned g_b0;    // basis-done arrivals
__device__ unsigned g_arr;   // partial-done arrivals
__device__ unsigned g_done;  // self-wrapping exit counter (resets the others)

__device__ __forceinline__ unsigned long long dupf(float v) {
    unsigned int b = __float_as_uint(v);
    return ((unsigned long long)b << 32) | (unsigned long long)b;
}
__device__ __forceinline__ void ffma2(unsigned long long& d,
                                      unsigned long long a,
                                      unsigned long long b) {
    asm("fma.rn.f32x2 %0, %1, %2, %0;" : "+l"(d) : "l"(a), "l"(b));
}
__device__ __forceinline__ float pick(unsigned long long u, int hi) {
    return __uint_as_float(hi ? (unsigned int)(u >> 32) : (unsigned int)u);
}

// ---------------------------------------------------------------------------
// Persistent kernel: basis -> grid barrier -> split-K GEMM (4b x 8o) ->
// grid barrier -> distributed reduce.  grid (38, 4) = 152 blocks, 256 thr.
// Static smem 48384 B (<= 48 KB): no attribute calls, 1 block/SM.
// ---------------------------------------------------------------------------
__global__ __launch_bounds__(256)
void kan_kernel(const float* __restrict__ x,
                const float* __restrict__ w,
                const float* __restrict__ c,
                float* __restrict__ out) {
    __shared__ float As[STAGE_KK * BATCH];    // [63][64]  = 16128 B
    __shared__ float Cs[STAGE_KK * OTILE];    // [63][128] = 32256 B

    const int s   = blockIdx.x;               // split-K index 0..37
    const int oy  = blockIdx.y;               // o-tile 0..3
    const int o0  = oy * OTILE;
    const int tid = threadIdx.x;
    const int blkLinear = oy * NSPLIT + s;    // 0..151

    // ===== Phase 0: basis (blocks 0..127 compute 4 i-columns each) =====
    if (blkLinear < IN_F / 4) {
        const int i0 = blkLinear * 4;
        const int di = tid & 3;
        const int b  = tid >> 2;
        float xv = x[b * IN_F + i0 + di];

        float sig = __fdividef(1.0f, 1.0f + __expf(-xv));
        float tt  = 1.0f - 2.0f * __fdividef(1.0f, 1.0f + __expf(2.0f * xv));
        tt = fminf(fmaxf(tt, -1.0f + 1e-6f), 1.0f - 1e-6f);

        float* s0 = As + di * (KB * SMSTRIDE) + b;   // alias As as scratch
        s0[0]        = xv * sig;   // silu slot
        s0[SMSTRIDE] = tt;         // T_1
        float tkm2 = 1.0f, tkm1 = tt;
        #pragma unroll
        for (int k = 2; k <= BASIS; k++) {
            float tk = 2.0f * tt * tkm1 - tkm2;
            s0[k * SMSTRIDE] = tk;
            tkm2 = tkm1; tkm1 = tk;
        }
        __syncthreads();

        // 36 rows x 16 float4 coalesced stores to g_A (scalar layout)
        for (int idx = tid; idx < 4 * KB * 16; idx += 256) {
            int row = idx >> 4;
            int c4  = idx & 15;
            const float* sr = As + row * SMSTRIDE + c4 * 4;
            float4 v = make_float4(sr[0], sr[1], sr[2], sr[3]);
            int di2 = row / KB, k2 = row % KB;
            ((float4*)(g_A + (i0 + di2) * (KB * BATCH) + k2 * BATCH))[c4] = v;
        }
        __syncthreads();
        if (tid == 0) { __threadfence(); atomicAdd(&g_b0, 1u); }
    }
    // grid-wide wait: basis complete
    if (tid == 0) { while (*(volatile unsigned*)&g_b0 != (unsigned)(IN_F / 4)) {} }
    __syncthreads();

    // ===== Phase 1: split-K GEMM, 4b x 8o micro-tiles =====
    const int og = tid & 15;      // o-group (16 groups x 8 o = 128)
    const int bg = tid >> 4;      // b-group (16 groups x 4 b = 64)
    const int ibeg = s * CHUNK;

    float4 aR[4];                 // A slab prefetch: 1008 float4 / 256 thr
    float  wR[4];
    float4 cR[4][2];

    unsigned long long acc[16];   // 4 b x 4 o-pairs
    #pragma unroll
    for (int j = 0; j < 16; j++) acc[j] = 0ull;

    auto loadStage = [&](int istS) {
        const float4* srcA = (const float4*)(g_A + (size_t)istS * (KB * BATCH));
        #pragma unroll
        for (int j = 0; j < 4; j++) {
            int d = tid + j * 256;
            aR[j] = (d < STAGE_KK * BATCH / 4) ? srcA[d]
                                               : make_float4(0.f, 0.f, 0.f, 0.f);
        }
        #pragma unroll
        for (int j = 0; j < 4; j++) {
            int p = tid + j * 256;            // 896 slots
            if (p < STAGE_I * OTILE) {
                int ii = p >> 7, oc = p & 127;
                int i = istS + ii;
                int o = o0 + oc;
                if (i < IN_F) {
                    wR[j] = w[i * OUT_F + o];
                    const float4* cp = (const float4*)(c + ((size_t)i * OUT_F + o) * BASIS);
                    cR[j][0] = cp[0];
                    cR[j][1] = cp[1];
                } else {
                    wR[j] = 0.f;
                    cR[j][0] = make_float4(0.f, 0.f, 0.f, 0.f);
                    cR[j][1] = make_float4(0.f, 0.f, 0.f, 0.f);
                }
            }
        }
    };

    auto storeStage = [&]() {
        #pragma unroll
        for (int j = 0; j < 4; j++) {
            int d = tid + j * 256;
            if (d < STAGE_KK * BATCH / 4) ((float4*)As)[d] = aR[j];
        }
        #pragma unroll
        for (int j = 0; j < 4; j++) {
            int p = tid + j * 256;
            if (p < STAGE_I * OTILE) {
                int ii = p >> 7, oc = p & 127;
                float* cs = Cs + ii * (KB * OTILE) + oc;
                float wv = wR[j];
                cs[0 * OTILE] = wv;
                cs[1 * OTILE] = cR[j][0].x * wv;
                cs[2 * OTILE] = cR[j][0].y * wv;
                cs[3 * OTILE] = cR[j][0].z * wv;
                cs[4 * OTILE] = cR[j][0].w * wv;
                cs[5 * OTILE] = cR[j][1].x * wv;
                cs[6 * OTILE] = cR[j][1].y * wv;
                cs[7 * OTILE] = cR[j][1].z * wv;
                cs[8 * OTILE] = cR[j][1].w * wv;
            }
        }
    };

    auto compute = [&]() {
        #pragma unroll 9
        for (int kk = 0; kk < STAGE_KK; kk++) {
            float4 av      = *(const float4*)&As[kk * BATCH + bg * 4];       // 4 b (bcast)
            ulonglong2 c01 = *(const ulonglong2*)&Cs[kk * OTILE + og * 8];   // o-pairs 0,1
            ulonglong2 c23 = *(const ulonglong2*)&Cs[kk * OTILE + og * 8 + 4];// o-pairs 2,3
            unsigned long long a0 = dupf(av.x), a1 = dupf(av.y);
            unsigned long long a2 = dupf(av.z), a3 = dupf(av.w);
            ffma2(acc[0],  a0, c01.x); ffma2(acc[1],  a0, c01.y);
            ffma2(acc[2],  a0, c23.x); ffma2(acc[3],  a0, c23.y);
            ffma2(acc[4],  a1, c01.x); ffma2(acc[5],  a1, c01.y);
            ffma2(acc[6],  a1, c23.x); ffma2(acc[7],  a1, c23.y);
            ffma2(acc[8],  a2, c01.x); ffma2(acc[9],  a2, c01.y);
            ffma2(acc[10], a2, c23.x); ffma2(acc[11], a2, c23.y);
            ffma2(acc[12], a3, c01.x); ffma2(acc[13], a3, c01.y);
            ffma2(acc[14], a3, c23.x); ffma2(acc[15], a3, c23.y);
        }
    };

    loadStage(ibeg);
    #pragma unroll
    for (int st = 0; st < NSTAGE; st++) {
        storeStage();
        __syncthreads();
        if (st < NSTAGE - 1) loadStage(ibeg + (st + 1) * STAGE_I);
        compute();
        __syncthreads();
    }

    // write split-K partial: 4 batches x 8 o per thread (2 coalesced float4)
    float* pout = g_part + (size_t)s * (BATCH * OUT_F);
    #pragma unroll
    for (int r = 0; r < 4; r++) {
        const int b = bg * 4 + r;
        float4 v0, v1;
        v0.x = pick(acc[r * 4 + 0], 0); v0.y = pick(acc[r * 4 + 0], 1);
        v0.z = pick(acc[r * 4 + 1], 0); v0.w = pick(acc[r * 4 + 1], 1);
        v1.x = pick(acc[r * 4 + 2], 0); v1.y = pick(acc[r * 4 + 2], 1);
        v1.z = pick(acc[r * 4 + 3], 0); v1.w = pick(acc[r * 4 + 3], 1);
        *(float4*)&pout[b * OUT_F + o0 + og * 8]     = v0;
        *(float4*)&pout[b * OUT_F + o0 + og * 8 + 4] = v1;
    }

    // ===== Phase 2: grid barrier, then distributed reduce =====
    __syncthreads();
    if (tid == 0) {
        __threadfence();
        atomicAdd(&g_arr, 1u);
        while (*(volatile unsigned*)&g_arr != (unsigned)TOTBLK) {}
    }
    __syncthreads();

    {
        const int slot = blkLinear * RED_CHUNK + tid;   // output float4 index
        if (tid < RED_CHUNK && slot < BATCH * OUT_F / 4) {
            const float4* gp = (const float4*)g_part;
            float4 sum = make_float4(0.f, 0.f, 0.f, 0.f);
            #pragma unroll
            for (int s2 = 0; s2 < NSPLIT; s2++) {
                float4 v = __ldcg(&gp[(size_t)s2 * (BATCH * OUT_F / 4) + slot]);
                sum.x += v.x; sum.y += v.y; sum.z += v.z; sum.w += v.w;
            }
            ((float4*)out)[slot] = sum;
        }
    }

    // reset counters for replay determinism (last block out resets)
    __syncthreads();
    if (tid == 0) {
        unsigned r = atomicInc(&g_done, TOTBLK - 1);   // wraps to 0
        if (r == TOTBLK - 1) {
            atomicExch(&g_arr, 0u);
            atomicExch(&g_b0, 0u);
        }
    }
}

// ---------------------------------------------------------------------------
extern "C" void kernel_launch(void* const* d_in, const int* in_sizes, int n_in,
                              void* d_out, int out_size) {
    const float* x = (const float*)d_in[0];   // (64, 512)
    const float* w = (const float*)d_in[1];   // (512, 512)
    const float* c = (const float*)d_in[2];   // (512, 512, 8)
    float* out = (float*)d_out;               // (64, 512)

    kan_kernel<<<dim3(NSPLIT, NOTILE), 256>>>(x, w, c, out);
}

// round 12
// speedup vs baseline: 1.2788x; 1.2749x over previous
#include <cuda_runtime.h>
#include <cuda_fp16.h>
#include <math.h>

#define BATCH    64
#define IN_F     512
#define OUT_F    512
#define BASIS    8
#define KB       9                   // 1 (silu/w slot) + BASIS
#define NSPLIT   38                  // split-K over i
#define CHUNK    14                  // 38*14 = 532 -> 20 zero-pad i-rows
#define STAGE_I  7
#define NSTAGE   2                   // 14 / 7
#define OTILE    128
#define STAGE_KK (STAGE_I * KB)      // 63
#define NOTILE   (OUT_F / OTILE)     // 4
#define TOTBLK   (NSPLIT * NOTILE)   // 152
#define NGROUP   (BATCH * OUT_F / 8) // 4096 8-half groups
#define RED_CHUNK 27                 // 27*152 = 4104 >= 4096

// fp16 split-K partials (2.5 MB) + barrier counters (bss-zero)
__device__ __half g_ph[NSPLIT * BATCH * OUT_F];
__device__ unsigned g_arr;   // partial-done arrivals
__device__ unsigned g_done;  // self-wrapping exit counter (resets g_arr)

__device__ __forceinline__ unsigned long long dupf(float v) {
    unsigned int b = __float_as_uint(v);
    return ((unsigned long long)b << 32) | (unsigned long long)b;
}
__device__ __forceinline__ void ffma2(unsigned long long& d,
                                      unsigned long long a,
                                      unsigned long long b) {
    asm("fma.rn.f32x2 %0, %1, %2, %0;" : "+l"(d) : "l"(a), "l"(b));
}
__device__ __forceinline__ unsigned packh2(unsigned long long u) {
    __half2 h = __floats2half2_rn(__uint_as_float((unsigned)u),
                                  __uint_as_float((unsigned)(u >> 32)));
    return *(unsigned*)&h;
}

// ---------------------------------------------------------------------------
// Persistent kernel: [per-stage: basis-in-block + CW staging -> compute] x2 ->
// grid barrier -> distributed reduce.  grid (38, 4) = 152 blocks, 256 thr.
// Static smem 48384 B; mainloop identical to the 17.2us R6 kernel.
// ---------------------------------------------------------------------------
__global__ __launch_bounds__(256)
void kan_kernel(const float* __restrict__ x,
                const float* __restrict__ w,
                const float* __restrict__ c,
                float* __restrict__ out) {
    __shared__ float As[STAGE_KK * BATCH];    // [63][64]  = 16128 B
    __shared__ float Cs[STAGE_KK * OTILE];    // [63][128] = 32256 B

    const int s   = blockIdx.x;               // split-K index 0..37
    const int oy  = blockIdx.y;               // o-tile 0..3
    const int o0  = oy * OTILE;
    const int tid = threadIdx.x;
    const int blkLinear = oy * NSPLIT + s;    // 0..151

    const int bb4 = (tid & 15) * 4;           // batch-fast (R6 mapping)
    const int oo8 = (tid >> 4) * 8;           // o-slow
    const int ibeg = s * CHUNK;

    float  xR[2];
    float  wR[4];
    float4 cR[4][2];

    unsigned long long acc[16];
    #pragma unroll
    for (int j = 0; j < 16; j++) acc[j] = 0ull;

    // ---- stage loaders (G -> regs) ----
    auto loadX = [&](int istS) {
        #pragma unroll
        for (int j = 0; j < 2; j++) {
            int idx = tid + j * 256;
            if (idx < STAGE_I * BATCH) {
                int ii = idx >> 6, b = idx & 63;
                int i = istS + ii;
                xR[j] = (i < IN_F) ? __ldg(&x[b * IN_F + i]) : 0.0f;
            }
        }
    };
    auto loadCW = [&](int istS) {
        #pragma unroll
        for (int j = 0; j < 4; j++) {
            int p = tid + j * 256;            // 896 slots
            if (p < STAGE_I * OTILE) {
                int ii = p >> 7, oc = p & 127;
                int i = istS + ii;
                int o = o0 + oc;
                if (i < IN_F) {
                    wR[j] = w[i * OUT_F + o];
                    const float4* cp = (const float4*)(c + ((size_t)i * OUT_F + o) * BASIS);
                    cR[j][0] = cp[0];
                    cR[j][1] = cp[1];
                } else {
                    wR[j] = 0.f;
                    cR[j][0] = make_float4(0.f, 0.f, 0.f, 0.f);
                    cR[j][1] = make_float4(0.f, 0.f, 0.f, 0.f);
                }
            }
        }
    };

    // ---- stage stores (regs -> smem); basis computed here ----
    auto storeA = [&]() {
        #pragma unroll
        for (int j = 0; j < 2; j++) {
            int idx = tid + j * 256;
            if (idx < STAGE_I * BATCH) {
                int ii = idx >> 6, b = idx & 63;
                float xv = xR[j];
                float sig = __fdividef(1.0f, 1.0f + __expf(-xv));
                float tt  = 1.0f - 2.0f * __fdividef(1.0f, 1.0f + __expf(2.0f * xv));
                tt = fminf(fmaxf(tt, -1.0f + 1e-6f), 1.0f - 1e-6f);
                float* s0 = As + (ii * KB) * BATCH + b;
                s0[0]     = xv * sig;     // silu slot (pairs with w)
                s0[BATCH] = tt;           // T_1
                float tkm2 = 1.0f, tkm1 = tt;
                #pragma unroll
                for (int k = 2; k <= BASIS; k++) {
                    float tk = 2.0f * tt * tkm1 - tkm2;
                    s0[k * BATCH] = tk;
                    tkm2 = tkm1; tkm1 = tk;
                }
            }
        }
    };
    auto storeCW = [&]() {
        #pragma unroll
        for (int j = 0; j < 4; j++) {
            int p = tid + j * 256;
            if (p < STAGE_I * OTILE) {
                int ii = p >> 7, oc = p & 127;
                float* cs = Cs + ii * (KB * OTILE) + oc;
                float wv = wR[j];
                cs[0 * OTILE] = wv;
                cs[1 * OTILE] = cR[j][0].x * wv;
                cs[2 * OTILE] = cR[j][0].y * wv;
                cs[3 * OTILE] = cR[j][0].z * wv;
                cs[4 * OTILE] = cR[j][0].w * wv;
                cs[5 * OTILE] = cR[j][1].x * wv;
                cs[6 * OTILE] = cR[j][1].y * wv;
                cs[7 * OTILE] = cR[j][1].z * wv;
                cs[8 * OTILE] = cR[j][1].w * wv;
            }
        }
    };

    // ---- mainloop (identical to R6 17.2us kernel) ----
    auto compute = [&]() {
        #pragma unroll 9
        for (int kk = 0; kk < STAGE_KK; kk++) {
            float4 av      = *(const float4*)&As[kk * BATCH + bb4];         // 4 b
            ulonglong2 c01 = *(const ulonglong2*)&Cs[kk * OTILE + oo8];     // o-pairs 0,1
            ulonglong2 c23 = *(const ulonglong2*)&Cs[kk * OTILE + oo8 + 4]; // o-pairs 2,3
            unsigned long long a0 = dupf(av.x), a1 = dupf(av.y);
            unsigned long long a2 = dupf(av.z), a3 = dupf(av.w);
            ffma2(acc[0],  a0, c01.x); ffma2(acc[1],  a0, c01.y);
            ffma2(acc[2],  a0, c23.x); ffma2(acc[3],  a0, c23.y);
            ffma2(acc[4],  a1, c01.x); ffma2(acc[5],  a1, c01.y);
            ffma2(acc[6],  a1, c23.x); ffma2(acc[7],  a1, c23.y);
            ffma2(acc[8],  a2, c01.x); ffma2(acc[9],  a2, c01.y);
            ffma2(acc[10], a2, c23.x); ffma2(acc[11], a2, c23.y);
            ffma2(acc[12], a3, c01.x); ffma2(acc[13], a3, c01.y);
            ffma2(acc[14], a3, c23.x); ffma2(acc[15], a3, c23.y);
        }
    };

    // software pipeline over 2 stages
    loadX(ibeg); loadCW(ibeg);
    #pragma unroll
    for (int st = 0; st < NSTAGE; st++) {
        storeA(); storeCW();
        __syncthreads();
        if (st < NSTAGE - 1) { loadX(ibeg + (st + 1) * STAGE_I); loadCW(ibeg + (st + 1) * STAGE_I); }
        compute();
        __syncthreads();
    }

    // ---- write split-K partial as fp16: 4 batches x 8 o per thread ----
    __half* ph = g_ph + (size_t)s * (BATCH * OUT_F);
    #pragma unroll
    for (int r = 0; r < 4; r++) {
        const int b = bb4 + r;
        uint4 v;
        v.x = packh2(acc[r * 4 + 0]);
        v.y = packh2(acc[r * 4 + 1]);
        v.z = packh2(acc[r * 4 + 2]);
        v.w = packh2(acc[r * 4 + 3]);
        *(uint4*)&ph[b * OUT_F + o0 + oo8] = v;
    }

    // ---- grid barrier, then distributed reduce (fp32 accumulate) ----
    __syncthreads();
    if (tid == 0) {
        __threadfence();
        atomicAdd(&g_arr, 1u);
        while (*(volatile unsigned*)&g_arr != (unsigned)TOTBLK) {}
    }
    __syncthreads();

    {
        const int grp = blkLinear * RED_CHUNK + tid;   // 8-half group index
        if (tid < RED_CHUNK && grp < NGROUP) {
            const uint4* gp = (const uint4*)g_ph;
            float2 s0 = make_float2(0.f, 0.f), s1 = s0, s2 = s0, s3 = s0;
            #pragma unroll
            for (int k = 0; k < NSPLIT; k++) {
                uint4 v = __ldcg(&gp[(size_t)k * NGROUP + grp]);
                float2 f0 = __half22float2(*(__half2*)&v.x);
                float2 f1 = __half22float2(*(__half2*)&v.y);
                float2 f2 = __half22float2(*(__half2*)&v.z);
                float2 f3 = __half22float2(*(__half2*)&v.w);
                s0.x += f0.x; s0.y += f0.y; s1.x += f1.x; s1.y += f1.y;
                s2.x += f2.x; s2.y += f2.y; s3.x += f3.x; s3.y += f3.y;
            }
            float4* op = (float4*)(out + grp * 8);
            op[0] = make_float4(s0.x, s0.y, s1.x, s1.y);
            op[1] = make_float4(s2.x, s2.y, s3.x, s3.y);
        }
    }

    // reset counters for replay determinism (last block out resets)
    __syncthreads();
    if (tid == 0) {
        unsigned r = atomicInc(&g_done, TOTBLK - 1);   // wraps to 0
        if (r == TOTBLK - 1) atomicExch(&g_arr, 0u);
    }
}

// ---------------------------------------------------------------------------
extern "C" void kernel_launch(void* const* d_in, const int* in_sizes, int n_in,
                              void* d_out, int out_size) {
    const float* x = (const float*)d_in[0];   // (64, 512)
    const float* w = (const float*)d_in[1];   // (512, 512)
    const float* c = (const float*)d_in[2];   // (512, 512, 8)
    float* out = (float*)d_out;               // (64, 512)

    kan_kernel<<<dim3(NSPLIT, NOTILE), 256>>>(x, w, c, out);
}